// round 2
// baseline (speedup 1.0000x reference)
#include <cuda_runtime.h>
#include <cstdint>

// ---------------------------------------------------------------------------
// GateMulti: out[b] = relu(x[b] @ W1[e] + b1[e]) @ W2[e] + b2[e],  e=groups[b,0]
// Strategy: bucket rows by expert, then two grouped tf32 tensor-core GEMMs.
// ---------------------------------------------------------------------------

namespace {
constexpr int NE    = 8;
constexpr int BATCH = 4096;
constexpr int DIN   = 512;
constexpr int DFF   = 2048;
constexpr int DOUT  = 512;

constexpr int BM = 128;
constexpr int BN = 64;
constexpr int BK = 32;
constexpr int MAX_TILES = 40;   // sum ceil(n_e/128) <= 4096/128 + 7 = 39
}

// Scratch (device globals: no runtime allocation allowed)
__device__ int   g_perm[BATCH];
__device__ int   g_tile_e[MAX_TILES];
__device__ int   g_tile_row0[MAX_TILES];
__device__ int   g_tile_rows[MAX_TILES];
__device__ int   g_ntiles;
__device__ float g_H[(size_t)BATCH * DFF];   // hidden activations, perm-ordered

// round-to-nearest tf32 (kept in f32 container; low 13 mantissa bits zero)
__device__ __forceinline__ float tf32r(float f) {
    unsigned r;
    asm("cvt.rna.tf32.f32 %0, %1;" : "=r"(r) : "f"(f));
    return __uint_as_float(r);
}

__device__ __forceinline__ void mma8(float* c, const unsigned* a, const unsigned* b) {
    asm volatile(
        "mma.sync.aligned.m16n8k8.row.col.f32.tf32.tf32.f32 "
        "{%0,%1,%2,%3}, {%4,%5,%6,%7}, {%8,%9}, {%0,%1,%2,%3};"
        : "+f"(c[0]), "+f"(c[1]), "+f"(c[2]), "+f"(c[3])
        : "r"(a[0]), "r"(a[1]), "r"(a[2]), "r"(a[3]), "r"(b[0]), "r"(b[1]));
}

// ---------------------------------------------------------------------------
// Setup: histogram experts, prefix-sum, scatter row indices, build tile table.
// Order within a bucket is nondeterministic but results are order-invariant.
// ---------------------------------------------------------------------------
__global__ void setup_kernel(const int* __restrict__ groups) {
    __shared__ int s_cnt[NE];
    __shared__ int s_cur[NE];
    const int tid = threadIdx.x;
    if (tid < NE) s_cnt[tid] = 0;
    __syncthreads();
    for (int i = tid; i < BATCH; i += blockDim.x)
        atomicAdd(&s_cnt[groups[2 * i]], 1);
    __syncthreads();
    if (tid == 0) {
        int base = 0, nt = 0;
        for (int e = 0; e < NE; e++) {
            s_cur[e] = base;
            const int c = s_cnt[e];
            for (int t0 = 0; t0 < c; t0 += BM) {
                g_tile_e[nt]    = e;
                g_tile_row0[nt] = base + t0;
                g_tile_rows[nt] = min(BM, c - t0);
                nt++;
            }
            base += c;
        }
        g_ntiles = nt;
    }
    __syncthreads();
    for (int i = tid; i < BATCH; i += blockDim.x) {
        const int e = groups[2 * i];
        const int p = atomicAdd(&s_cur[e], 1);
        g_perm[p] = i;
    }
}

// ---------------------------------------------------------------------------
// Grouped GEMM. PHASE 1: H = relu(gather(x) @ W1[e] + b1[e])  (K=512,  N=2048)
//               PHASE 2: out[perm] = H @ W2[e] + b2[e]        (K=2048, N=512)
// CTA tile 128x64, BK=32, 8 warps in 4(m) x 2(n), warp tile 32x32,
// m16n8k8 tf32 mma. Smem strides 36 / 72 words: conflict-free fragment LDS.
// ---------------------------------------------------------------------------
template <int PHASE>
__global__ void __launch_bounds__(256)
gemm_kernel(const float* __restrict__ Ag,
            const float* __restrict__ Bg,
            const float* __restrict__ bias,
            float* __restrict__ outp) {
    constexpr int Kd = (PHASE == 1) ? DIN : DFF;
    constexpr int Nd = (PHASE == 1) ? DFF : DOUT;

    const int tile = blockIdx.x;
    if (tile >= g_ntiles) return;
    const int e    = g_tile_e[tile];
    const int row0 = g_tile_row0[tile];
    const int rows = g_tile_rows[tile];
    const int n0   = blockIdx.y * BN;

    __shared__ __align__(16) float As[BM][36];   // stride 36: 4*row+col banks
    __shared__ __align__(16) float Bs[BK][72];   // stride 72: 8*k+n banks
    __shared__ int s_src[BM];

    const int tid = threadIdx.x;
    const float* Aptr = (PHASE == 1) ? Ag : g_H;

    if (tid < BM) {
        int idx;
        if (PHASE == 1)
            idx = (tid < rows) ? g_perm[row0 + tid] : g_perm[row0];
        else
            idx = (tid < rows) ? (row0 + tid) : row0;
        s_src[tid] = idx;
    }
    __syncthreads();

    const float* Bbase = Bg + (size_t)e * Kd * Nd + n0;

    const int a_c = tid & 7,  a_r = tid >> 3;   // A: 8 float4-chunks x 32 rows/pass
    const int b_c = tid & 15, b_r = tid >> 4;   // B: 16 float4-chunks x 16 rows/pass

    const int warp = tid >> 5;
    const int lane = tid & 31;
    const int wm = warp & 3;        // warp row tile (32 rows)
    const int wn = warp >> 2;       // warp col tile (32 cols)
    const int g  = lane >> 2, tg = lane & 3;

    float acc[2][4][4];
    #pragma unroll
    for (int mi = 0; mi < 2; mi++)
        #pragma unroll
        for (int ni = 0; ni < 4; ni++)
            #pragma unroll
            for (int q = 0; q < 4; q++) acc[mi][ni][q] = 0.f;

    for (int kt = 0; kt < Kd; kt += BK) {
        // ---- load A tile (gathered rows; rna-round to tf32 in phase 1) ----
        #pragma unroll
        for (int p = 0; p < 4; p++) {
            const int lr = a_r + p * 32;
            const float4 v = *reinterpret_cast<const float4*>(
                Aptr + (size_t)s_src[lr] * Kd + kt + a_c * 4);
            float4 w = v;
            if (PHASE == 1) {
                w.x = tf32r(v.x); w.y = tf32r(v.y);
                w.z = tf32r(v.z); w.w = tf32r(v.w);
            }
            *reinterpret_cast<float4*>(&As[lr][a_c * 4]) = w;
        }
        // ---- load B tile (weights; always rna-round) ----
        #pragma unroll
        for (int p = 0; p < 2; p++) {
            const int lr = b_r + p * 16;
            const float4 v = *reinterpret_cast<const float4*>(
                Bbase + (size_t)(kt + lr) * Nd + b_c * 4);
            float4 w;
            w.x = tf32r(v.x); w.y = tf32r(v.y);
            w.z = tf32r(v.z); w.w = tf32r(v.w);
            *reinterpret_cast<float4*>(&Bs[lr][b_c * 4]) = w;
        }
        __syncthreads();

        // ---- 4 k-steps of m16n8k8 ----
        #pragma unroll
        for (int kk = 0; kk < 4; kk++) {
            const int k0 = kk * 8;
            unsigned a[2][4], b[4][2];
            #pragma unroll
            for (int mi = 0; mi < 2; mi++) {
                const int rb = wm * 32 + mi * 16;
                a[mi][0] = __float_as_uint(As[rb + g    ][k0 + tg    ]);
                a[mi][1] = __float_as_uint(As[rb + g + 8][k0 + tg    ]);
                a[mi][2] = __float_as_uint(As[rb + g    ][k0 + tg + 4]);
                a[mi][3] = __float_as_uint(As[rb + g + 8][k0 + tg + 4]);
            }
            #pragma unroll
            for (int ni = 0; ni < 4; ni++) {
                const int cb = wn * 32 + ni * 8 + g;
                b[ni][0] = __float_as_uint(Bs[k0 + tg    ][cb]);
                b[ni][1] = __float_as_uint(Bs[k0 + tg + 4][cb]);
            }
            #pragma unroll
            for (int mi = 0; mi < 2; mi++)
                #pragma unroll
                for (int ni = 0; ni < 4; ni++)
                    mma8(acc[mi][ni], a[mi], b[ni]);
        }
        __syncthreads();
    }

    // ---- epilogue: bias (+ relu + tf32 round for phase 1), guarded store ----
    #pragma unroll
    for (int mi = 0; mi < 2; mi++) {
        #pragma unroll
        for (int ni = 0; ni < 4; ni++) {
            const int col = n0 + wn * 32 + ni * 8 + tg * 2;
            const float2 bv = *reinterpret_cast<const float2*>(
                bias + (size_t)e * Nd + col);
            #pragma unroll
            for (int h = 0; h < 2; h++) {
                const int lr = wm * 32 + mi * 16 + g + h * 8;
                if (lr < rows) {
                    float v0 = acc[mi][ni][h * 2 + 0] + bv.x;
                    float v1 = acc[mi][ni][h * 2 + 1] + bv.y;
                    if (PHASE == 1) {
                        v0 = v0 > 0.f ? v0 : 0.f;
                        v1 = v1 > 0.f ? v1 : 0.f;
                        // pre-round so phase-2 A path needs no conversion
                        float2 o = {tf32r(v0), tf32r(v1)};
                        *reinterpret_cast<float2*>(
                            &g_H[(size_t)(row0 + lr) * DFF + col]) = o;
                    } else {
                        const int orow = g_perm[row0 + lr];
                        float2 o = {v0, v1};
                        *reinterpret_cast<float2*>(
                            &outp[(size_t)orow * DOUT + col]) = o;
                    }
                }
            }
        }
    }
}

// ---------------------------------------------------------------------------
// Launch: setup -> GEMM1 (40 x 32 CTAs) -> GEMM2 (40 x 8 CTAs). Graph-safe.
// Input order per metadata: x, groups, W1, b1, W2, b2.
// ---------------------------------------------------------------------------
extern "C" void kernel_launch(void* const* d_in, const int* in_sizes, int n_in,
                              void* d_out, int out_size) {
    const float* x      = (const float*)d_in[0];
    const int*   groups = (const int*)  d_in[1];
    const float* W1     = (const float*)d_in[2];
    const float* b1     = (const float*)d_in[3];
    const float* W2     = (const float*)d_in[4];
    const float* b2     = (const float*)d_in[5];
    float*       out    = (float*)d_out;
    (void)in_sizes; (void)n_in; (void)out_size;

    setup_kernel<<<1, 256>>>(groups);
    gemm_kernel<1><<<dim3(MAX_TILES, DFF / BN), 256>>>(x, W1, b1, nullptr);
    gemm_kernel<2><<<dim3(MAX_TILES, DOUT / BN), 256>>>(x, W2, b2, out);
}

// round 4
// speedup vs baseline: 1.2510x; 1.2510x over previous
#include <cuda_runtime.h>
#include <cstdint>

// ---------------------------------------------------------------------------
// GateMulti: out[b] = relu(x[b] @ W1[e] + b1[e]) @ W2[e] + b2[e],  e=groups[b,0]
// Round 3: bucket rows by expert, then two grouped tf32 tensor-core GEMMs with
// a 3-stage cp.async pipeline, 128x128 CTA tiles, 64x32 warp tiles.
// ---------------------------------------------------------------------------

namespace {
constexpr int NE    = 8;
constexpr int BATCH = 4096;
constexpr int DIN   = 512;
constexpr int DFF   = 2048;
constexpr int DOUT  = 512;

constexpr int BM = 128;
constexpr int BN = 128;
constexpr int BK = 32;
constexpr int STAGES = 3;
constexpr int MAX_TILES = 40;       // sum ceil(n_e/128) <= 4096/128 + 7 = 39

constexpr int ASTRIDE = 36;         // 36 % 32 == 4  -> conflict-free A frags
constexpr int BSTRIDE = 136;        // 136 % 32 == 8 -> conflict-free B frags
constexpr int A_ELEMS = BM * ASTRIDE;
constexpr int B_ELEMS = BK * BSTRIDE;
constexpr size_t SMEM_BYTES = (size_t)STAGES * (A_ELEMS + B_ELEMS) * sizeof(float);
}

// Scratch (device globals: no runtime allocation allowed)
__device__ int   g_perm[BATCH];
__device__ int   g_tile_e[MAX_TILES];
__device__ int   g_tile_row0[MAX_TILES];
__device__ int   g_tile_rows[MAX_TILES];
__device__ int   g_ntiles;
__device__ float g_H[(size_t)BATCH * DFF];    // hidden acts, perm order, tf32-rounded
__device__ float g_Xr[(size_t)BATCH * DIN];   // x, tf32-rounded

__device__ __forceinline__ float tf32r(float f) {
    unsigned r;
    asm("cvt.rna.tf32.f32 %0, %1;" : "=r"(r) : "f"(f));
    return __uint_as_float(r);
}
__device__ __forceinline__ unsigned tf32r_bits(float f) {
    unsigned r;
    asm("cvt.rna.tf32.f32 %0, %1;" : "=r"(r) : "f"(f));
    return r;
}

__device__ __forceinline__ void cp16(float* dst_smem, const float* src) {
    unsigned d = (unsigned)__cvta_generic_to_shared(dst_smem);
    asm volatile("cp.async.cg.shared.global [%0], [%1], 16;\n" :: "r"(d), "l"(src));
}
__device__ __forceinline__ void cp_commit() {
    asm volatile("cp.async.commit_group;\n" ::: "memory");
}
template <int N>
__device__ __forceinline__ void cp_wait() {
    asm volatile("cp.async.wait_group %0;\n" :: "n"(N) : "memory");
}

__device__ __forceinline__ void mma8(float* c, const unsigned* a, const unsigned* b) {
    asm volatile(
        "mma.sync.aligned.m16n8k8.row.col.f32.tf32.tf32.f32 "
        "{%0,%1,%2,%3}, {%4,%5,%6,%7}, {%8,%9}, {%0,%1,%2,%3};"
        : "+f"(c[0]), "+f"(c[1]), "+f"(c[2]), "+f"(c[3])
        : "r"(a[0]), "r"(a[1]), "r"(a[2]), "r"(a[3]), "r"(b[0]), "r"(b[1]));
}

// ---------------------------------------------------------------------------
// Setup: bucket rows by expert, build tile table.
// ---------------------------------------------------------------------------
__global__ void setup_kernel(const int* __restrict__ groups) {
    __shared__ int s_cnt[NE];
    __shared__ int s_cur[NE];
    const int tid = threadIdx.x;
    if (tid < NE) s_cnt[tid] = 0;
    __syncthreads();
    for (int i = tid; i < BATCH; i += blockDim.x)
        atomicAdd(&s_cnt[groups[2 * i]], 1);
    __syncthreads();
    if (tid == 0) {
        int base = 0, nt = 0;
        for (int e = 0; e < NE; e++) {
            s_cur[e] = base;
            const int c = s_cnt[e];
            for (int t0 = 0; t0 < c; t0 += BM) {
                g_tile_e[nt]    = e;
                g_tile_row0[nt] = base + t0;
                g_tile_rows[nt] = min(BM, c - t0);
                nt++;
            }
            base += c;
        }
        g_ntiles = nt;
    }
    __syncthreads();
    for (int i = tid; i < BATCH; i += blockDim.x) {
        const int e = groups[2 * i];
        const int p = atomicAdd(&s_cur[e], 1);
        g_perm[p] = i;
    }
}

// Pre-round x to tf32 (one float4 per thread).
__global__ void round_x_kernel(const float* __restrict__ x) {
    const int i = blockIdx.x * blockDim.x + threadIdx.x;
    float4 v = reinterpret_cast<const float4*>(x)[i];
    v.x = tf32r(v.x); v.y = tf32r(v.y); v.z = tf32r(v.z); v.w = tf32r(v.w);
    reinterpret_cast<float4*>(g_Xr)[i] = v;
}

// ---------------------------------------------------------------------------
// Grouped GEMM, 3-stage cp.async pipeline.
// PHASE 1: H = relu(gather(Xr) @ W1[e] + b1[e])   K=512,  N=2048
// PHASE 2: out[perm] = H @ W2[e] + b2[e]          K=2048, N=512
// 8 warps: 2(m) x 4(n), warp tile 64x32, m16n8k8 tf32.
// ---------------------------------------------------------------------------
template <int PHASE>
__global__ void __launch_bounds__(256)
gemm_kernel(const float* __restrict__ Bg,
            const float* __restrict__ bias,
            float* __restrict__ outp) {
    constexpr int Kd = (PHASE == 1) ? DIN : DFF;
    constexpr int Nd = (PHASE == 1) ? DFF : DOUT;

    extern __shared__ float smem[];
    float* AsBase = smem;                        // [STAGES][BM][ASTRIDE]
    float* BsBase = smem + STAGES * A_ELEMS;     // [STAGES][BK][BSTRIDE]
    __shared__ int s_src[BM];
    __shared__ int s_out[BM];

    const int tile = blockIdx.x;
    if (tile >= g_ntiles) return;
    const int e    = g_tile_e[tile];
    const int row0 = g_tile_row0[tile];
    const int rows = g_tile_rows[tile];
    const int n0   = blockIdx.y * BN;

    const int tid = threadIdx.x;
    const float* Aptr = (PHASE == 1) ? g_Xr : g_H;

    if (tid < BM) {
        const int p = row0 + min(tid, rows - 1);   // clamp OOB rows to a valid one
        s_src[tid] = (PHASE == 1) ? g_perm[p] : p;
        if (PHASE == 2) s_out[tid] = g_perm[p];
    }
    __syncthreads();

    const float* Bbase = Bg + (size_t)e * Kd * Nd + n0;

    // loader mapping: A = 32 rows x 8 float4-chunks per pass (4 passes),
    //                 B = 8 rows x 32 float4-chunks per pass (4 passes)
    const int a_c = tid & 7,  a_r = tid >> 3;
    const int b_c = tid & 31, b_r = tid >> 5;

    auto load_stage = [&](int kt, int s) {
        float* As = AsBase + s * A_ELEMS;
        float* Bs = BsBase + s * B_ELEMS;
        #pragma unroll
        for (int p = 0; p < 4; p++) {
            const int lr = a_r + p * 32;
            cp16(As + lr * ASTRIDE + a_c * 4,
                 Aptr + (size_t)s_src[lr] * Kd + kt + a_c * 4);
        }
        #pragma unroll
        for (int p = 0; p < 4; p++) {
            const int lr = b_r + p * 8;
            cp16(Bs + lr * BSTRIDE + b_c * 4,
                 Bbase + (size_t)(kt + lr) * Nd + b_c * 4);
        }
    };

    const int warp = tid >> 5;
    const int lane = tid & 31;
    const int wm = warp & 1;          // 2 warps over M (64 rows each)
    const int wn = warp >> 1;         // 4 warps over N (32 cols each)
    const int g  = lane >> 2, tg = lane & 3;

    float acc[4][4][4];
    #pragma unroll
    for (int mi = 0; mi < 4; mi++)
        #pragma unroll
        for (int ni = 0; ni < 4; ni++)
            #pragma unroll
            for (int q = 0; q < 4; q++) acc[mi][ni][q] = 0.f;

    // prologue: prefetch STAGES-1 tiles
    #pragma unroll
    for (int s = 0; s < STAGES - 1; s++) {
        load_stage(s * BK, s);
        cp_commit();
    }

    int smem_s = 0;
    for (int kt = 0; kt < Kd; kt += BK) {
        cp_wait<STAGES - 2>();
        __syncthreads();

        const int kt_next = kt + (STAGES - 1) * BK;
        if (kt_next < Kd) {
            const int s_next = (smem_s + STAGES - 1 < STAGES)
                                   ? smem_s + STAGES - 1
                                   : smem_s + STAGES - 1 - STAGES;
            load_stage(kt_next, s_next);
        }
        cp_commit();    // commit every iter (possibly empty) to keep counts aligned

        const float* As = AsBase + smem_s * A_ELEMS;
        const float* Bs = BsBase + smem_s * B_ELEMS;

        #pragma unroll
        for (int kk = 0; kk < 4; kk++) {
            const int k0 = kk * 8;
            unsigned a[4][4], b[4][2];
            #pragma unroll
            for (int mi = 0; mi < 4; mi++) {
                const int rb = wm * 64 + mi * 16;
                a[mi][0] = __float_as_uint(As[(rb + g    ) * ASTRIDE + k0 + tg    ]);
                a[mi][1] = __float_as_uint(As[(rb + g + 8) * ASTRIDE + k0 + tg    ]);
                a[mi][2] = __float_as_uint(As[(rb + g    ) * ASTRIDE + k0 + tg + 4]);
                a[mi][3] = __float_as_uint(As[(rb + g + 8) * ASTRIDE + k0 + tg + 4]);
            }
            #pragma unroll
            for (int ni = 0; ni < 4; ni++) {
                const int cb = wn * 32 + ni * 8 + g;
                // weights arrive raw f32: rna-round in register
                b[ni][0] = tf32r_bits(Bs[(k0 + tg    ) * BSTRIDE + cb]);
                b[ni][1] = tf32r_bits(Bs[(k0 + tg + 4) * BSTRIDE + cb]);
            }
            #pragma unroll
            for (int mi = 0; mi < 4; mi++)
                #pragma unroll
                for (int ni = 0; ni < 4; ni++)
                    mma8(acc[mi][ni], a[mi], b[ni]);
        }

        smem_s = (smem_s + 1 == STAGES) ? 0 : smem_s + 1;
        __syncthreads();
    }

    // ---- epilogue ----
    #pragma unroll
    for (int mi = 0; mi < 4; mi++) {
        #pragma unroll
        for (int ni = 0; ni < 4; ni++) {
            const int col = n0 + wn * 32 + ni * 8 + tg * 2;
            const float2 bv = *reinterpret_cast<const float2*>(
                bias + (size_t)e * Nd + col);
            #pragma unroll
            for (int h = 0; h < 2; h++) {
                const int lr = wm * 64 + mi * 16 + g + h * 8;
                if (lr < rows) {
                    float v0 = acc[mi][ni][h * 2 + 0] + bv.x;
                    float v1 = acc[mi][ni][h * 2 + 1] + bv.y;
                    if (PHASE == 1) {
                        v0 = v0 > 0.f ? v0 : 0.f;
                        v1 = v1 > 0.f ? v1 : 0.f;
                        float2 o = {tf32r(v0), tf32r(v1)};   // pre-round for GEMM2 A path
                        *reinterpret_cast<float2*>(
                            &g_H[(size_t)(row0 + lr) * DFF + col]) = o;
                    } else {
                        float2 o = {v0, v1};
                        *reinterpret_cast<float2*>(
                            &outp[(size_t)s_out[lr] * DOUT + col]) = o;
                    }
                }
            }
        }
    }
}

// ---------------------------------------------------------------------------
// Launch: setup + round_x -> GEMM1 -> GEMM2. Graph-safe, allocation-free.
// Inputs per metadata: x, groups, W1, b1, W2, b2.
// ---------------------------------------------------------------------------
extern "C" void kernel_launch(void* const* d_in, const int* in_sizes, int n_in,
                              void* d_out, int out_size) {
    const float* x      = (const float*)d_in[0];
    const int*   groups = (const int*)  d_in[1];
    const float* W1     = (const float*)d_in[2];
    const float* b1     = (const float*)d_in[3];
    const float* W2     = (const float*)d_in[4];
    const float* b2     = (const float*)d_in[5];
    float*       out    = (float*)d_out;
    (void)in_sizes; (void)n_in; (void)out_size;

    cudaFuncSetAttribute(gemm_kernel<1>,
                         cudaFuncAttributeMaxDynamicSharedMemorySize, (int)SMEM_BYTES);
    cudaFuncSetAttribute(gemm_kernel<2>,
                         cudaFuncAttributeMaxDynamicSharedMemorySize, (int)SMEM_BYTES);

    setup_kernel<<<1, 256>>>(groups);
    round_x_kernel<<<(BATCH * DIN / 4) / 256, 256>>>(x);
    gemm_kernel<1><<<dim3(MAX_TILES, DFF / BN), 256, SMEM_BYTES>>>(W1, b1, nullptr);
    gemm_kernel<2><<<dim3(MAX_TILES, DOUT / BN), 256, SMEM_BYTES>>>(W2, b2, out);
}

// round 5
// speedup vs baseline: 1.7452x; 1.3950x over previous
#include <cuda_runtime.h>
#include <cstdint>

// ---------------------------------------------------------------------------
// GateMulti: out[b] = relu(x[b] @ W1[e] + b1[e]) @ W2[e] + b2[e],  e=groups[b,0]
// Round 5: grouped tf32 mma.sync GEMMs, 3-stage cp.async pipeline, one barrier
// per iter; GEMM2 uses deterministic split-K=2 + reduce to fix grid starvation.
// ---------------------------------------------------------------------------

namespace {
constexpr int NE    = 8;
constexpr int BATCH = 4096;
constexpr int DIN   = 512;
constexpr int DFF   = 2048;
constexpr int DOUT  = 512;

constexpr int BM = 128;
constexpr int BN = 128;
constexpr int BK = 32;
constexpr int STAGES = 3;
constexpr int SPLITK2 = 2;          // split-K factor for GEMM2
constexpr int MAX_TILES = 40;       // sum ceil(n_e/128) <= 4096/128 + 7 = 39

constexpr int ASTRIDE = 36;         // 36 % 32 == 4  -> conflict-free A frags
constexpr int BSTRIDE = 136;        // 136 % 32 == 8 -> conflict-free B frags
constexpr int A_ELEMS = BM * ASTRIDE;
constexpr int B_ELEMS = BK * BSTRIDE;
constexpr size_t SMEM_BYTES = (size_t)STAGES * (A_ELEMS + B_ELEMS) * sizeof(float);
}

// Scratch (device globals: no runtime allocation allowed)
__device__ int   g_perm[BATCH];
__device__ int   g_row_e[BATCH];                    // expert of perm position
__device__ int   g_tile_e[MAX_TILES];
__device__ int   g_tile_row0[MAX_TILES];
__device__ int   g_tile_rows[MAX_TILES];
__device__ int   g_ntiles;
__device__ float g_H[(size_t)BATCH * DFF];          // hidden acts, perm order
__device__ float g_Xr[(size_t)BATCH * DIN];         // x, tf32-rounded
__device__ float g_P[(size_t)SPLITK2 * BATCH * DOUT];  // GEMM2 partials, perm order

__device__ __forceinline__ float tf32r(float f) {
    unsigned r;
    asm("cvt.rna.tf32.f32 %0, %1;" : "=r"(r) : "f"(f));
    return __uint_as_float(r);
}
__device__ __forceinline__ unsigned tf32r_bits(float f) {
    unsigned r;
    asm("cvt.rna.tf32.f32 %0, %1;" : "=r"(r) : "f"(f));
    return r;
}

__device__ __forceinline__ void cp16(float* dst_smem, const float* src) {
    unsigned d = (unsigned)__cvta_generic_to_shared(dst_smem);
    asm volatile("cp.async.cg.shared.global [%0], [%1], 16;\n" :: "r"(d), "l"(src));
}
__device__ __forceinline__ void cp_commit() {
    asm volatile("cp.async.commit_group;\n" ::: "memory");
}
template <int N>
__device__ __forceinline__ void cp_wait() {
    asm volatile("cp.async.wait_group %0;\n" :: "n"(N) : "memory");
}

__device__ __forceinline__ void mma8(float* c, const unsigned* a, const unsigned* b) {
    asm volatile(
        "mma.sync.aligned.m16n8k8.row.col.f32.tf32.tf32.f32 "
        "{%0,%1,%2,%3}, {%4,%5,%6,%7}, {%8,%9}, {%0,%1,%2,%3};"
        : "+f"(c[0]), "+f"(c[1]), "+f"(c[2]), "+f"(c[3])
        : "r"(a[0]), "r"(a[1]), "r"(a[2]), "r"(a[3]), "r"(b[0]), "r"(b[1]));
}

// ---------------------------------------------------------------------------
// Setup: bucket rows by expert (warp-aggregated atomics), build tile table.
// ---------------------------------------------------------------------------
__global__ void setup_kernel(const int* __restrict__ groups) {
    __shared__ int s_cnt[NE];
    __shared__ int s_cur[NE];
    const int tid  = threadIdx.x;
    const int lane = tid & 31;
    if (tid < NE) s_cnt[tid] = 0;
    __syncthreads();
    // 4096 / 256 = 16 full iterations: all lanes always active.
    for (int i = tid; i < BATCH; i += blockDim.x) {
        const int e = groups[2 * i];
        const unsigned mask = __match_any_sync(0xffffffffu, e);
        if (lane == (__ffs(mask) - 1)) atomicAdd(&s_cnt[e], __popc(mask));
    }
    __syncthreads();
    if (tid == 0) {
        int base = 0, nt = 0;
        for (int e = 0; e < NE; e++) {
            s_cur[e] = base;
            const int c = s_cnt[e];
            for (int t0 = 0; t0 < c; t0 += BM) {
                g_tile_e[nt]    = e;
                g_tile_row0[nt] = base + t0;
                g_tile_rows[nt] = min(BM, c - t0);
                nt++;
            }
            base += c;
        }
        g_ntiles = nt;
    }
    __syncthreads();
    for (int i = tid; i < BATCH; i += blockDim.x) {
        const int e = groups[2 * i];
        const unsigned mask = __match_any_sync(0xffffffffu, e);
        const int leader = __ffs(mask) - 1;
        const int rank   = __popc(mask & ((1u << lane) - 1));
        int base = 0;
        if (lane == leader) base = atomicAdd(&s_cur[e], __popc(mask));
        base = __shfl_sync(0xffffffffu, base, leader);
        const int p = base + rank;
        g_perm[p]  = i;
        g_row_e[p] = e;
    }
}

// Pre-round x to tf32 (one float4 per thread).
__global__ void round_x_kernel(const float* __restrict__ x) {
    const int i = blockIdx.x * blockDim.x + threadIdx.x;
    float4 v = reinterpret_cast<const float4*>(x)[i];
    v.x = tf32r(v.x); v.y = tf32r(v.y); v.z = tf32r(v.z); v.w = tf32r(v.w);
    reinterpret_cast<float4*>(g_Xr)[i] = v;
}

// ---------------------------------------------------------------------------
// Grouped GEMM, 3-stage cp.async pipeline, single barrier per iteration.
// PHASE 1: H = relu(gather(Xr) @ W1[e] + b1[e])       K=512,  N=2048
// PHASE 2: P[kz] = H @ W2[e]   (split-K=2, no bias)   K=1024, N=512
// 8 warps: 2(m) x 4(n), warp tile 64x32, m16n8k8 tf32.
// ---------------------------------------------------------------------------
template <int PHASE>
__global__ void __launch_bounds__(256, 2)
gemm_kernel(const float* __restrict__ Bg,
            const float* __restrict__ bias,
            float* __restrict__ outp) {
    constexpr int Kd   = (PHASE == 1) ? DIN : DFF;
    constexpr int Nd   = (PHASE == 1) ? DFF : DOUT;
    constexpr int KLEN = (PHASE == 1) ? Kd : (Kd / SPLITK2);
    constexpr int NITER = KLEN / BK;

    extern __shared__ float smem[];
    float* AsBase = smem;                        // [STAGES][BM][ASTRIDE]
    float* BsBase = smem + STAGES * A_ELEMS;     // [STAGES][BK][BSTRIDE]
    __shared__ int s_src[BM];

    const int tile = blockIdx.x;
    if (tile >= g_ntiles) return;
    const int e    = g_tile_e[tile];
    const int row0 = g_tile_row0[tile];
    const int rows = g_tile_rows[tile];
    const int n0   = blockIdx.y * BN;
    const int kt0  = (PHASE == 2) ? blockIdx.z * KLEN : 0;

    const int tid = threadIdx.x;
    const float* Aptr = (PHASE == 1) ? g_Xr : g_H;

    if (tid < BM) {
        const int p = row0 + min(tid, rows - 1);   // clamp OOB rows to a valid one
        s_src[tid] = (PHASE == 1) ? g_perm[p] : p;
    }
    __syncthreads();

    const float* Bbase = Bg + (size_t)e * Kd * Nd + n0;

    // loader mapping: A = 32 rows x 8 float4-chunks per pass (4 passes),
    //                 B = 8 rows x 32 float4-chunks per pass (4 passes)
    const int a_c = tid & 7,  a_r = tid >> 3;
    const int b_c = tid & 31, b_r = tid >> 5;

    auto load_stage = [&](int kt, int s) {
        float* As = AsBase + s * A_ELEMS;
        float* Bs = BsBase + s * B_ELEMS;
        #pragma unroll
        for (int p = 0; p < 4; p++) {
            const int lr = a_r + p * 32;
            cp16(As + lr * ASTRIDE + a_c * 4,
                 Aptr + (size_t)s_src[lr] * Kd + kt + a_c * 4);
        }
        #pragma unroll
        for (int p = 0; p < 4; p++) {
            const int lr = b_r + p * 8;
            cp16(Bs + lr * BSTRIDE + b_c * 4,
                 Bbase + (size_t)(kt + lr) * Nd + b_c * 4);
        }
    };

    const int warp = tid >> 5;
    const int lane = tid & 31;
    const int wm = warp & 1;          // 2 warps over M (64 rows each)
    const int wn = warp >> 1;         // 4 warps over N (32 cols each)
    const int g  = lane >> 2, tg = lane & 3;

    float acc[4][4][4];
    #pragma unroll
    for (int mi = 0; mi < 4; mi++)
        #pragma unroll
        for (int ni = 0; ni < 4; ni++)
            #pragma unroll
            for (int q = 0; q < 4; q++) acc[mi][ni][q] = 0.f;

    // prologue: prefetch STAGES-1 tiles
    #pragma unroll
    for (int s = 0; s < STAGES - 1; s++) {
        load_stage(kt0 + s * BK, s);
        cp_commit();
    }

    int smem_s = 0;
    for (int it = 0; it < NITER; it++) {
        cp_wait<STAGES - 2>();
        __syncthreads();   // all warps done reading stage (it-1)%3 => safe to refill

        const int it_next = it + (STAGES - 1);
        if (it_next < NITER) {
            const int s_next = (smem_s + STAGES - 1 < STAGES)
                                   ? smem_s + STAGES - 1
                                   : smem_s + STAGES - 1 - STAGES;
            load_stage(kt0 + it_next * BK, s_next);
        }
        cp_commit();    // commit every iter (possibly empty) to keep counts aligned

        const float* As = AsBase + smem_s * A_ELEMS;
        const float* Bs = BsBase + smem_s * B_ELEMS;

        #pragma unroll
        for (int kk = 0; kk < 4; kk++) {
            const int k0 = kk * 8;
            unsigned a[4][4], b[4][2];
            #pragma unroll
            for (int mi = 0; mi < 4; mi++) {
                const int rb = wm * 64 + mi * 16;
                a[mi][0] = __float_as_uint(As[(rb + g    ) * ASTRIDE + k0 + tg    ]);
                a[mi][1] = __float_as_uint(As[(rb + g + 8) * ASTRIDE + k0 + tg    ]);
                a[mi][2] = __float_as_uint(As[(rb + g    ) * ASTRIDE + k0 + tg + 4]);
                a[mi][3] = __float_as_uint(As[(rb + g + 8) * ASTRIDE + k0 + tg + 4]);
            }
            #pragma unroll
            for (int ni = 0; ni < 4; ni++) {
                const int cb = wn * 32 + ni * 8 + g;
                // weights arrive raw f32: rna-round in register
                b[ni][0] = tf32r_bits(Bs[(k0 + tg    ) * BSTRIDE + cb]);
                b[ni][1] = tf32r_bits(Bs[(k0 + tg + 4) * BSTRIDE + cb]);
            }
            #pragma unroll
            for (int mi = 0; mi < 4; mi++)
                #pragma unroll
                for (int ni = 0; ni < 4; ni++)
                    mma8(acc[mi][ni], a[mi], b[ni]);
        }

        smem_s = (smem_s + 1 == STAGES) ? 0 : smem_s + 1;
    }

    // ---- epilogue ----
    #pragma unroll
    for (int mi = 0; mi < 4; mi++) {
        #pragma unroll
        for (int ni = 0; ni < 4; ni++) {
            const int col = n0 + wn * 32 + ni * 8 + tg * 2;
            float2 bv = {0.f, 0.f};
            if (PHASE == 1)
                bv = *reinterpret_cast<const float2*>(bias + (size_t)e * Nd + col);
            #pragma unroll
            for (int h = 0; h < 2; h++) {
                const int lr = wm * 64 + mi * 16 + g + h * 8;
                if (lr < rows) {
                    float v0 = acc[mi][ni][h * 2 + 0] + bv.x;
                    float v1 = acc[mi][ni][h * 2 + 1] + bv.y;
                    if (PHASE == 1) {
                        v0 = v0 > 0.f ? v0 : 0.f;
                        v1 = v1 > 0.f ? v1 : 0.f;
                        float2 o = {tf32r(v0), tf32r(v1)};   // pre-round for GEMM2 A path
                        *reinterpret_cast<float2*>(
                            &g_H[(size_t)(row0 + lr) * DFF + col]) = o;
                    } else {
                        // partial, perm-ordered; bias added in reduce
                        float2 o = {v0, v1};
                        *reinterpret_cast<float2*>(
                            &g_P[(size_t)blockIdx.z * BATCH * DOUT +
                                 (size_t)(row0 + lr) * DOUT + col]) = o;
                    }
                }
            }
        }
    }
}

// ---------------------------------------------------------------------------
// Reduce: out[perm[r]] = P0[r] + P1[r] + b2[e(r)].  Fixed order: deterministic.
// ---------------------------------------------------------------------------
__global__ void reduce_kernel(const float* __restrict__ b2,
                              float* __restrict__ outp) {
    const int i  = blockIdx.x * blockDim.x + threadIdx.x;   // over 4096*128 float4
    const int r  = i >> 7;
    const int c  = (i & 127) << 2;
    const float4 p0 = *reinterpret_cast<const float4*>(&g_P[(size_t)r * DOUT + c]);
    const float4 p1 = *reinterpret_cast<const float4*>(
        &g_P[(size_t)BATCH * DOUT + (size_t)r * DOUT + c]);
    const int e = g_row_e[r];
    const float4 bv = *reinterpret_cast<const float4*>(&b2[(size_t)e * DOUT + c]);
    float4 o;
    o.x = p0.x + p1.x + bv.x;
    o.y = p0.y + p1.y + bv.y;
    o.z = p0.z + p1.z + bv.z;
    o.w = p0.w + p1.w + bv.w;
    *reinterpret_cast<float4*>(&outp[(size_t)g_perm[r] * DOUT + c]) = o;
}

// ---------------------------------------------------------------------------
// Launch graph-safe, allocation-free. Inputs: x, groups, W1, b1, W2, b2.
// ---------------------------------------------------------------------------
extern "C" void kernel_launch(void* const* d_in, const int* in_sizes, int n_in,
                              void* d_out, int out_size) {
    const float* x      = (const float*)d_in[0];
    const int*   groups = (const int*)  d_in[1];
    const float* W1     = (const float*)d_in[2];
    const float* b1     = (const float*)d_in[3];
    const float* W2     = (const float*)d_in[4];
    const float* b2     = (const float*)d_in[5];
    float*       out    = (float*)d_out;
    (void)in_sizes; (void)n_in; (void)out_size;

    cudaFuncSetAttribute(gemm_kernel<1>,
                         cudaFuncAttributeMaxDynamicSharedMemorySize, (int)SMEM_BYTES);
    cudaFuncSetAttribute(gemm_kernel<2>,
                         cudaFuncAttributeMaxDynamicSharedMemorySize, (int)SMEM_BYTES);

    setup_kernel<<<1, 256>>>(groups);
    round_x_kernel<<<(BATCH * DIN / 4) / 256, 256>>>(x);
    gemm_kernel<1><<<dim3(MAX_TILES, DFF / BN), 256, SMEM_BYTES>>>(W1, b1, nullptr);
    gemm_kernel<2><<<dim3(MAX_TILES, DOUT / BN, SPLITK2), 256, SMEM_BYTES>>>(
        W2, nullptr, nullptr);
    reduce_kernel<<<(BATCH * DOUT / 4) / 256, 256>>>(b2, out);
}